// round 1
// baseline (speedup 1.0000x reference)
#include <cuda_runtime.h>
#include <cuda_bf16.h>
#include <cstdint>

#define BQ    2048
#define DIM   1024
#define NROW  4096
#define XROWS 4224
#define TINV  14.285714285714285f   // 1/T, also the max possible logit (unit vectors)

// ---------------- scratch (device globals; no allocations allowed) ----------------
__device__ __nv_bfloat16 g_X[(size_t)XROWS * DIM];   // anchor rows + prev protos, bf16
__device__ float g_pointsdot[NROW];                  // replaced diagonal, already /T
__device__ int   g_lab[NROW];                        // rep_labels
__device__ float g_acc[7][NROW];                     // E, P0, P1, Pe, Pex, Pe2, Pe2x
__device__ float g_loss[2];                          // [0]=sum normal, [1]=sum samix

// ---------------- init: zero accumulators, build rep_labels ----------------
__global__ void init_k(const int* __restrict__ labels)
{
    int i = blockIdx.x * blockDim.x + threadIdx.x;
    if (i < NROW) {
        g_lab[i] = labels[i & (BQ - 1)];
#pragma unroll
        for (int q = 0; q < 7; ++q) g_acc[q][i] = 0.f;
    }
    if (i == 0) { g_loss[0] = 0.f; g_loss[1] = 0.f; }
}

// ---------------- build bf16 X = [anchor(4096) ; prev_proto(PREV) ; zeros] ----------------
__global__ void prep_X(const float* __restrict__ feats,
                       const float* __restrict__ points,
                       const int* __restrict__ prevp)
{
    const int PREV = prevp ? *prevp : 100;
    int idx = blockIdx.x * blockDim.x + threadIdx.x;  // one thread per 4 elements
    int r = idx >> 8;
    int c = (idx & 255) << 2;
    if (r >= XROWS) return;
    float4 v = make_float4(0.f, 0.f, 0.f, 0.f);
    if (r < NROW) {
        const float* src = feats + ((r < BQ) ? (size_t)r * (2 * DIM)
                                             : (size_t)(r - BQ) * (2 * DIM) + DIM);
        v = *(const float4*)(src + c);
    } else if (r < NROW + PREV) {
        v = *(const float4*)(points + (size_t)(r - NROW) * DIM + c);
    }
    union { uint2 u; __nv_bfloat162 h[2]; } o;
    o.h[0] = __floats2bfloat162_rn(v.x, v.y);
    o.h[1] = __floats2bfloat162_rn(v.z, v.w);
    *(uint2*)(g_X + (size_t)r * DIM + c) = o.u;
}

// ---------------- diagonal replacement: anchor_i . points[label_i] / T (fp32) ----------------
__global__ void pointsdot_k(const float* __restrict__ feats,
                            const float* __restrict__ points)
{
    int r = blockIdx.x * 8 + (threadIdx.x >> 5);
    int lane = threadIdx.x & 31;
    if (r >= NROW) return;
    const float* a = feats + ((r < BQ) ? (size_t)r * (2 * DIM)
                                       : (size_t)(r - BQ) * (2 * DIM) + DIM);
    const float* p = points + (size_t)g_lab[r] * DIM;
    float s = 0.f;
    for (int k = lane * 4; k < DIM; k += 128) {
        float4 av = *(const float4*)(a + k);
        float4 pv = *(const float4*)(p + k);
        s += av.x * pv.x + av.y * pv.y + av.z * pv.z + av.w * pv.w;
    }
#pragma unroll
    for (int o = 16; o > 0; o >>= 1) s += __shfl_xor_sync(0xffffffffu, s, o);
    if (lane == 0) g_pointsdot[r] = s * TINV;
}

// ---------------- fused GEMM (bf16 mma.sync) + focal-contrastive epilogue ----------------
// S[i][j] = X[i].X[j]/T for i<4096, j<4096+PREV. Per row accumulate:
//   E    = sum_{j!=i, j<NCOLS} exp(l - 1/T)                     (denominator)
//   over positives (label match, j<4096, incl. diag w/ replaced logit):
//   P0=sum 1, P1=sum x, Pe=sum e, Pex=sum e*x, Pe2=sum e^2, Pe2x=sum e^2*x
__global__ __launch_bounds__(256) void gemm_epi(const int* __restrict__ prevp)
{
    __shared__ __nv_bfloat16 As[2][128][40];   // +8 pad -> conflict-free ldmatrix
    __shared__ __nv_bfloat16 Bs[2][128][40];

    const int PREV  = prevp ? *prevp : 100;
    const int NCOLS = NROW + PREV;
    const int row0  = blockIdx.y * 128;
    const int col0  = blockIdx.x * 128;

    const int t = threadIdx.x;
    const int lane = t & 31, wid = t >> 5;
    const int wr = wid >> 1, wc = wid & 1;   // 4x2 warp grid: 32 rows x 64 cols per warp

    float acc[2][8][4];
#pragma unroll
    for (int a = 0; a < 2; a++)
#pragma unroll
        for (int b = 0; b < 8; b++)
#pragma unroll
            for (int c = 0; c < 4; c++) acc[a][b][c] = 0.f;

    auto issue = [&](int it, int buf) {
        int k0 = it * 32;
#pragma unroll
        for (int h = 0; h < 2; ++h) {
            int p = t + h * 256;
            int r = p >> 2, s = p & 3;
            const __nv_bfloat16* ga = g_X + (size_t)(row0 + r) * DIM + k0 + s * 8;
            const __nv_bfloat16* gb = g_X + (size_t)(col0 + r) * DIM + k0 + s * 8;
            uint32_t sa = (uint32_t)__cvta_generic_to_shared(&As[buf][r][s * 8]);
            uint32_t sb = (uint32_t)__cvta_generic_to_shared(&Bs[buf][r][s * 8]);
            asm volatile("cp.async.cg.shared.global [%0], [%1], 16;" :: "r"(sa), "l"(ga));
            asm volatile("cp.async.cg.shared.global [%0], [%1], 16;" :: "r"(sb), "l"(gb));
        }
        asm volatile("cp.async.commit_group;");
    };

    issue(0, 0);
#pragma unroll 1
    for (int it = 0; it < 32; ++it) {
        int buf = it & 1;
        if (it < 31) {
            issue(it + 1, buf ^ 1);
            asm volatile("cp.async.wait_group 1;");
        } else {
            asm volatile("cp.async.wait_group 0;");
        }
        __syncthreads();
#pragma unroll
        for (int kk = 0; kk < 2; ++kk) {
            uint32_t a[2][4];
#pragma unroll
            for (int mt = 0; mt < 2; ++mt) {
                uint32_t addr = (uint32_t)__cvta_generic_to_shared(
                    &As[buf][wr * 32 + mt * 16 + (lane & 15)][kk * 16 + ((lane >> 4) << 3)]);
                asm volatile("ldmatrix.sync.aligned.m8n8.x4.shared.b16 {%0,%1,%2,%3}, [%4];"
                             : "=r"(a[mt][0]), "=r"(a[mt][1]), "=r"(a[mt][2]), "=r"(a[mt][3])
                             : "r"(addr));
            }
            uint32_t b[8][2];
#pragma unroll
            for (int nt2 = 0; nt2 < 4; ++nt2) {
                int n_off = wc * 64 + nt2 * 16 + (lane & 7) + ((lane & 16) >> 1);
                int k_off = kk * 16 + (lane & 8);
                uint32_t addr = (uint32_t)__cvta_generic_to_shared(&Bs[buf][n_off][k_off]);
                uint32_t r0, r1, r2, r3;
                asm volatile("ldmatrix.sync.aligned.m8n8.x4.shared.b16 {%0,%1,%2,%3}, [%4];"
                             : "=r"(r0), "=r"(r1), "=r"(r2), "=r"(r3) : "r"(addr));
                b[2 * nt2][0] = r0; b[2 * nt2][1] = r1;
                b[2 * nt2 + 1][0] = r2; b[2 * nt2 + 1][1] = r3;
            }
#pragma unroll
            for (int mt = 0; mt < 2; ++mt)
#pragma unroll
                for (int nt = 0; nt < 8; ++nt)
                    asm volatile("mma.sync.aligned.m16n8k16.row.col.f32.bf16.bf16.f32 "
                                 "{%0,%1,%2,%3},{%4,%5,%6,%7},{%8,%9},{%0,%1,%2,%3};"
                                 : "+f"(acc[mt][nt][0]), "+f"(acc[mt][nt][1]),
                                   "+f"(acc[mt][nt][2]), "+f"(acc[mt][nt][3])
                                 : "r"(a[mt][0]), "r"(a[mt][1]), "r"(a[mt][2]), "r"(a[mt][3]),
                                   "r"(b[nt][0]), "r"(b[nt][1]));
        }
        __syncthreads();
    }

    // -------- epilogue: per-row 7 sums, shifted by M = 1/T --------
    float sums[4][7];
#pragma unroll
    for (int rs = 0; rs < 4; rs++)
#pragma unroll
        for (int q = 0; q < 7; q++) sums[rs][q] = 0.f;

    int irow[4], labi[4];
#pragma unroll
    for (int rs = 0; rs < 4; rs++) {
        int mt = rs >> 1, half = rs & 1;
        irow[rs] = row0 + wr * 32 + mt * 16 + half * 8 + (lane >> 2);
        labi[rs] = g_lab[irow[rs]];
    }
#pragma unroll
    for (int mt = 0; mt < 2; ++mt)
#pragma unroll
        for (int nt = 0; nt < 8; ++nt)
#pragma unroll
            for (int c = 0; c < 4; ++c) {
                int half = c >> 1;
                int rs = mt * 2 + half;
                int i = irow[rs];
                int j = col0 + wc * 64 + nt * 8 + ((lane & 3) * 2) + (c & 1);
                if (j < NCOLS) {
                    float l = acc[mt][nt][c] * TINV;
                    bool diag = (i == j);
                    if (diag) l = g_pointsdot[i];
                    float x = l - TINV;
                    float e = expf(x);
                    if (!diag) sums[rs][0] += e;
                    if (j < NROW && labi[rs] == g_lab[j]) {
                        sums[rs][1] += 1.0f;
                        sums[rs][2] += x;
                        sums[rs][3] += e;
                        float ex = e * x;
                        sums[rs][4] += ex;
                        float e2 = e * e;
                        sums[rs][5] += e2;
                        sums[rs][6] += e2 * x;
                    }
                }
            }
#pragma unroll
    for (int rs = 0; rs < 4; rs++)
#pragma unroll
        for (int q = 0; q < 7; q++) {
            float v = sums[rs][q];
            v += __shfl_xor_sync(0xffffffffu, v, 1);
            v += __shfl_xor_sync(0xffffffffu, v, 2);
            if ((lane & 3) == 0) atomicAdd(&g_acc[q][irow[rs]], v);
        }
}

// ---------------- samix / slerp branch ----------------
__global__ void samix_k(const float* __restrict__ sf, const float* __restrict__ points,
                        const float* __restrict__ lambp, const int* __restrict__ labels,
                        const int* __restrict__ mixed)
{
    int r = blockIdx.x * 8 + (threadIdx.x >> 5);
    int lane = threadIdx.x & 31;
    if (r >= NROW) return;
    int lr = labels[r & (BQ - 1)];
    int mi = mixed[r];
    int lp = labels[mi & (BQ - 1)];
    const float* corr = points + (size_t)lr * DIM;
    const float* perm = points + (size_t)lp * DIM;
    const float* s = sf + (size_t)r * DIM;
    float dcp = 0.f, dsc = 0.f, dsp = 0.f;
    for (int k = lane * 4; k < DIM; k += 128) {
        float4 c = *(const float4*)(corr + k);
        float4 p = *(const float4*)(perm + k);
        float4 v = *(const float4*)(s + k);
        dcp += c.x * p.x + c.y * p.y + c.z * p.z + c.w * p.w;
        dsc += v.x * c.x + v.y * c.y + v.z * c.z + v.w * c.w;
        dsp += v.x * p.x + v.y * p.y + v.z * p.z + v.w * p.w;
    }
#pragma unroll
    for (int o = 16; o > 0; o >>= 1) {
        dcp += __shfl_xor_sync(0xffffffffu, dcp, o);
        dsc += __shfl_xor_sync(0xffffffffu, dsc, o);
        dsp += __shfl_xor_sync(0xffffffffu, dsp, o);
    }
    if (lane == 0) {
        float lamb = *lambp;
        float cost = fminf(1.f, fmaxf(-1.f, dcp));
        float theta = acosf(cost);
        float sval;
        if (theta < 1e-6f) {
            sval = dsc;
        } else {
            float st = sinf(theta);
            sval = (sinf(lamb * theta) / st) * dsc + (sinf((1.f - lamb) * theta) / st) * dsp;
        }
        float d = sval - 1.f;
        atomicAdd(&g_loss[1], 0.5f * d * d);
    }
}

// ---------------- per-row finalize of the contrastive loss ----------------
__global__ void finalize_k(const int* __restrict__ labels,
                           const int* __restrict__ tlab, int ntl)
{
    int i = blockIdx.x * blockDim.x + threadIdx.x;
    int lane = threadIdx.x & 31;
    float val = 0.f;
    if (i < NROW) {
        float Dn = g_acc[0][i];
        float P0 = g_acc[1][i], P1 = g_acc[2][i], Pe = g_acc[3][i];
        float Pex = g_acc[4][i], Pe2 = g_acc[5][i], Pe2x = g_acc[6][i];
        float LD = logf(Dn);
        float inv = 1.f / Dn;
        float w0 = P0 - 2.f * Pe * inv + Pe2 * inv * inv;
        float wx = P1 - 2.f * Pex * inv + Pe2x * inv * inv;
        float S = wx - LD * w0;
        float pos = (P0 < 1e-6f) ? 1.f : P0;
        float mlpp = -S / pos;
        int li = labels[i & (BQ - 1)];
        bool curr = false;
        for (int k = 0; k < ntl; ++k) curr |= (tlab[k] == li);
        val = curr ? mlpp : 0.f;
    }
#pragma unroll
    for (int o = 16; o > 0; o >>= 1) val += __shfl_xor_sync(0xffffffffu, val, o);
    if (lane == 0) atomicAdd(&g_loss[0], val);
}

__global__ void combine_k(float* __restrict__ out)
{
    if (threadIdx.x == 0)
        out[0] = (g_loss[0] + g_loss[1]) * (1.0f / (float)NROW);
}

// ---------------- launch ----------------
extern "C" void kernel_launch(void* const* d_in, const int* in_sizes, int n_in,
                              void* d_out, int out_size)
{
    const float* features = (const float*)d_in[0];
    const float* samix    = (const float*)d_in[1];
    const float* points   = (const float*)d_in[2];
    const float* lamb     = (const float*)d_in[3];
    const int*   labels   = (const int*)d_in[4];
    const int*   tlab     = (const int*)d_in[5];
    const int*   mixed    = (const int*)d_in[6];
    const int*   prevp    = (n_in > 7) ? (const int*)d_in[7] : nullptr;
    int ntl = in_sizes[5];

    init_k<<<(NROW + 255) / 256, 256>>>(labels);
    prep_X<<<(XROWS * DIM / 4 + 255) / 256, 256>>>(features, points, prevp);
    pointsdot_k<<<NROW / 8, 256>>>(features, points);
    gemm_epi<<<dim3(XROWS / 128, NROW / 128), 256>>>(prevp);
    samix_k<<<NROW / 8, 256>>>(samix, points, lamb, labels, mixed);
    finalize_k<<<(NROW + 255) / 256, 256>>>(labels, tlab, ntl);
    combine_k<<<1, 32>>>((float*)d_out);
    (void)out_size;
}

// round 3
// speedup vs baseline: 1.6329x; 1.6329x over previous
#include <cuda_runtime.h>
#include <cuda_bf16.h>
#include <cstdint>

#define BQ    2048
#define DIM   1024
#define NROW  4096
#define XROWS 4224
#define NTILR 32            // row tiles (4096/128)
#define NTILC 33            // col tiles (4224/128)
#define TINV  14.285714285714285f
#define LOG2E 1.4426950408889634f
#define C1EXP (TINV * LOG2E)       // e^{(a-1)/T} = 2^{a*C1 - C1}
#define BCAP  64

// ---------------- scratch (device globals) ----------------
__device__ __nv_bfloat16 g_X[(size_t)XROWS * DIM];
__device__ float g_pointsdot[NROW];   // diag replacement, already *1/T
__device__ int   g_lab[NROW];
__device__ float g_acc[7][NROW];      // [0]=E  [1..6]=P0,P1,Pe,Pex,Pe2,Pe2x
__device__ float g_loss[2];
__device__ int   g_cnt[1000];
__device__ int   g_bucket[1000 * BCAP];

__device__ __forceinline__ float ex2f(float y)
{
    float r;
    asm("ex2.approx.ftz.f32 %0, %1;" : "=f"(r) : "f"(y));
    return r;
}

// ---------------- init ----------------
__global__ void init_k(const int* __restrict__ labels)
{
    int i = blockIdx.x * blockDim.x + threadIdx.x;
    if (i < NROW) {
        g_lab[i] = labels[i & (BQ - 1)];
        g_acc[0][i] = 0.f;
    }
    if (i < 1000) g_cnt[i] = 0;
    if (i == 0) { g_loss[0] = 0.f; g_loss[1] = 0.f; }
}

__global__ void bucket_k(const int* __restrict__ labels)
{
    int b = blockIdx.x * blockDim.x + threadIdx.x;
    if (b >= BQ) return;
    int lab = labels[b];
    int idx = atomicAdd(&g_cnt[lab], 1);
    if (idx < BCAP) g_bucket[lab * BCAP + idx] = b;
}

// ---------------- X = [anchor(4096) ; prev_proto ; zeros], bf16 ----------------
__global__ void prep_X(const float* __restrict__ feats,
                       const float* __restrict__ points,
                       const int* __restrict__ prevp)
{
    const int PREV = prevp ? *prevp : 100;
    int idx = blockIdx.x * blockDim.x + threadIdx.x;
    int r = idx >> 8;
    int c = (idx & 255) << 2;
    if (r >= XROWS) return;
    float4 v = make_float4(0.f, 0.f, 0.f, 0.f);
    if (r < NROW) {
        const float* src = feats + ((r < BQ) ? (size_t)r * (2 * DIM)
                                             : (size_t)(r - BQ) * (2 * DIM) + DIM);
        v = *(const float4*)(src + c);
    } else if (r < NROW + PREV) {
        v = *(const float4*)(points + (size_t)(r - NROW) * DIM + c);
    }
    union { uint2 u; __nv_bfloat162 h[2]; } o;
    o.h[0] = __floats2bfloat162_rn(v.x, v.y);
    o.h[1] = __floats2bfloat162_rn(v.z, v.w);
    *(uint2*)(g_X + (size_t)r * DIM + c) = o.u;
}

// ---------------- diag replacement: anchor_i . points[label_i] / T (fp32 exact) ----------------
__global__ void pointsdot_k(const float* __restrict__ feats,
                            const float* __restrict__ points)
{
    int r = blockIdx.x * 8 + (threadIdx.x >> 5);
    int lane = threadIdx.x & 31;
    if (r >= NROW) return;
    const float* a = feats + ((r < BQ) ? (size_t)r * (2 * DIM)
                                       : (size_t)(r - BQ) * (2 * DIM) + DIM);
    const float* p = points + (size_t)g_lab[r] * DIM;
    float s = 0.f;
    for (int k = lane * 4; k < DIM; k += 128) {
        float4 av = *(const float4*)(a + k);
        float4 pv = *(const float4*)(p + k);
        s += av.x * pv.x + av.y * pv.y + av.z * pv.z + av.w * pv.w;
    }
#pragma unroll
    for (int o = 16; o > 0; o >>= 1) s += __shfl_xor_sync(0xffffffffu, s, o);
    if (lane == 0) g_pointsdot[r] = s * TINV;
}

// ---------------- symmetric GEMM + denominator epilogue ----------------
// Only tiles (r,c) with c>=r. Off-diag strict tiles feed both E[row] and E[col].
// Diagonal elements (i==j) are excluded from E exactly (reference logits_mask).
__global__ __launch_bounds__(256, 2) void gemm_epi(const int* __restrict__ prevp)
{
    __shared__ __nv_bfloat16 As[2][128][40];
    __shared__ __nv_bfloat16 Bs[2][128][40];

    const int PREV  = prevp ? *prevp : 100;
    const int NCOLS = NROW + PREV;

    // map linear block id -> upper-triangular (r,c)
    int t = blockIdx.x, r = 0;
    while (t >= NTILC - r) { t -= NTILC - r; ++r; }
    const int c = r + t;
    const int row0 = r * 128;
    const int col0 = c * 128;
    const int tile_type = (c == NTILC - 1) ? 2 : (c == r ? 0 : 1);  // 0 diag, 1 strict, 2 prev

    const int tid = threadIdx.x;
    const int lane = tid & 31, wid = tid >> 5;
    const int wr = wid >> 1, wc = wid & 1;

    float acc[2][8][4];
#pragma unroll
    for (int a = 0; a < 2; a++)
#pragma unroll
        for (int b = 0; b < 8; b++)
#pragma unroll
            for (int q = 0; q < 4; q++) acc[a][b][q] = 0.f;

    auto issue = [&](int it, int buf) {
        int k0 = it * 32;
#pragma unroll
        for (int h = 0; h < 2; ++h) {
            int p = tid + h * 256;
            int rr = p >> 2, s = p & 3;
            const __nv_bfloat16* ga = g_X + (size_t)(row0 + rr) * DIM + k0 + s * 8;
            const __nv_bfloat16* gb = g_X + (size_t)(col0 + rr) * DIM + k0 + s * 8;
            uint32_t sa = (uint32_t)__cvta_generic_to_shared(&As[buf][rr][s * 8]);
            uint32_t sb = (uint32_t)__cvta_generic_to_shared(&Bs[buf][rr][s * 8]);
            asm volatile("cp.async.cg.shared.global [%0], [%1], 16;" :: "r"(sa), "l"(ga));
            asm volatile("cp.async.cg.shared.global [%0], [%1], 16;" :: "r"(sb), "l"(gb));
        }
        asm volatile("cp.async.commit_group;");
    };

    issue(0, 0);
#pragma unroll 1
    for (int it = 0; it < 32; ++it) {
        int buf = it & 1;
        if (it < 31) {
            issue(it + 1, buf ^ 1);
            asm volatile("cp.async.wait_group 1;");
        } else {
            asm volatile("cp.async.wait_group 0;");
        }
        __syncthreads();
#pragma unroll
        for (int kk = 0; kk < 2; ++kk) {
            uint32_t a[2][4];
#pragma unroll
            for (int mt = 0; mt < 2; ++mt) {
                uint32_t addr = (uint32_t)__cvta_generic_to_shared(
                    &As[buf][wr * 32 + mt * 16 + (lane & 15)][kk * 16 + ((lane >> 4) << 3)]);
                asm volatile("ldmatrix.sync.aligned.m8n8.x4.shared.b16 {%0,%1,%2,%3}, [%4];"
                             : "=r"(a[mt][0]), "=r"(a[mt][1]), "=r"(a[mt][2]), "=r"(a[mt][3])
                             : "r"(addr));
            }
            uint32_t b[8][2];
#pragma unroll
            for (int nt2 = 0; nt2 < 4; ++nt2) {
                int n_off = wc * 64 + nt2 * 16 + (lane & 7) + ((lane & 16) >> 1);
                int k_off = kk * 16 + (lane & 8);
                uint32_t addr = (uint32_t)__cvta_generic_to_shared(&Bs[buf][n_off][k_off]);
                uint32_t r0, r1, r2, r3;
                asm volatile("ldmatrix.sync.aligned.m8n8.x4.shared.b16 {%0,%1,%2,%3}, [%4];"
                             : "=r"(r0), "=r"(r1), "=r"(r2), "=r"(r3) : "r"(addr));
                b[2 * nt2][0] = r0; b[2 * nt2][1] = r1;
                b[2 * nt2 + 1][0] = r2; b[2 * nt2 + 1][1] = r3;
            }
#pragma unroll
            for (int mt = 0; mt < 2; ++mt)
#pragma unroll
                for (int nt = 0; nt < 8; ++nt)
                    asm volatile("mma.sync.aligned.m16n8k16.row.col.f32.bf16.bf16.f32 "
                                 "{%0,%1,%2,%3},{%4,%5,%6,%7},{%8,%9},{%0,%1,%2,%3};"
                                 : "+f"(acc[mt][nt][0]), "+f"(acc[mt][nt][1]),
                                   "+f"(acc[mt][nt][2]), "+f"(acc[mt][nt][3])
                                 : "r"(a[mt][0]), "r"(a[mt][1]), "r"(a[mt][2]), "r"(a[mt][3]),
                                   "r"(b[nt][0]), "r"(b[nt][1]));
        }
        __syncthreads();
    }

    // -------- epilogue: denominator only --------
    float rowE[4] = {0.f, 0.f, 0.f, 0.f};
    float colE[16];
#pragma unroll
    for (int q = 0; q < 16; q++) colE[q] = 0.f;

    int irow[4];
#pragma unroll
    for (int rs = 0; rs < 4; rs++)
        irow[rs] = row0 + wr * 32 + (rs >> 1) * 16 + (rs & 1) * 8 + (lane >> 2);

#pragma unroll
    for (int mt = 0; mt < 2; ++mt)
#pragma unroll
        for (int nt = 0; nt < 8; ++nt)
#pragma unroll
            for (int q = 0; q < 4; ++q) {
                int rs = mt * 2 + (q >> 1);
                float e = ex2f(fmaf(acc[mt][nt][q], C1EXP, -C1EXP));
                if (tile_type != 1) {
                    int j = col0 + wc * 64 + nt * 8 + (lane & 3) * 2 + (q & 1);
                    if (tile_type == 2) { if (j >= NCOLS) e = 0.f; }
                    else                { if (j == irow[rs]) e = 0.f; }  // exact diag exclusion
                }
                rowE[rs] += e;
                colE[nt * 2 + (q & 1)] += e;
            }

#pragma unroll
    for (int rs = 0; rs < 4; rs++) {
        float v = rowE[rs];
        v += __shfl_xor_sync(0xffffffffu, v, 1);
        v += __shfl_xor_sync(0xffffffffu, v, 2);
        if ((lane & 3) == 0) atomicAdd(&g_acc[0][irow[rs]], v);
    }
    if (tile_type == 1) {
#pragma unroll
        for (int idx = 0; idx < 16; ++idx) {
            float v = colE[idx];
            v += __shfl_xor_sync(0xffffffffu, v, 4);
            v += __shfl_xor_sync(0xffffffffu, v, 8);
            v += __shfl_xor_sync(0xffffffffu, v, 16);
            if (lane < 4) {
                int j = col0 + wc * 64 + (idx >> 1) * 8 + lane * 2 + (idx & 1);
                atomicAdd(&g_acc[0][j], v);
            }
        }
    }
}

// ---------------- sparse positive pass: per row, ~9 same-label pairs ----------------
__global__ void pos_k()
{
    int i = blockIdx.x * 8 + (threadIdx.x >> 5);
    int lane = threadIdx.x & 31;
    if (i >= NROW) return;
    int lab = g_lab[i];
    int cnt = g_cnt[lab];
    if (cnt > BCAP) cnt = BCAP;

    const uint2* xi = (const uint2*)(g_X + (size_t)i * DIM);
    float rif[32];
#pragma unroll
    for (int k = 0; k < 8; ++k) {
        uint2 u = xi[lane + 32 * k];
        float2 f0 = __bfloat1622float2(*(const __nv_bfloat162*)&u.x);
        float2 f1 = __bfloat1622float2(*(const __nv_bfloat162*)&u.y);
        rif[k * 4 + 0] = f0.x; rif[k * 4 + 1] = f0.y;
        rif[k * 4 + 2] = f1.x; rif[k * 4 + 3] = f1.y;
    }

    float P0 = 0.f, P1 = 0.f, Pe = 0.f, Pex = 0.f, Pe2 = 0.f, Pe2x = 0.f;
    for (int b = 0; b < cnt; ++b) {
        int base = g_bucket[lab * BCAP + b];
#pragma unroll
        for (int v = 0; v < 2; ++v) {
            int j = base + v * BQ;
            float x;
            if (j == i) {
                x = g_pointsdot[i] - TINV;
            } else {
                const uint2* xj = (const uint2*)(g_X + (size_t)j * DIM);
                float d = 0.f;
#pragma unroll
                for (int k = 0; k < 8; ++k) {
                    uint2 u = xj[lane + 32 * k];
                    float2 f0 = __bfloat1622float2(*(const __nv_bfloat162*)&u.x);
                    float2 f1 = __bfloat1622float2(*(const __nv_bfloat162*)&u.y);
                    d = fmaf(rif[k * 4 + 0], f0.x, d);
                    d = fmaf(rif[k * 4 + 1], f0.y, d);
                    d = fmaf(rif[k * 4 + 2], f1.x, d);
                    d = fmaf(rif[k * 4 + 3], f1.y, d);
                }
#pragma unroll
                for (int o = 16; o > 0; o >>= 1) d += __shfl_xor_sync(0xffffffffu, d, o);
                x = fmaf(d, TINV, -TINV);
            }
            float e = ex2f(x * LOG2E);
            P0 += 1.f; P1 += x; Pe += e;
            Pex += e * x; Pe2 += e * e; Pe2x += e * e * x;
        }
    }
    if (lane == 0) {
        g_acc[1][i] = P0; g_acc[2][i] = P1; g_acc[3][i] = Pe;
        g_acc[4][i] = Pex; g_acc[5][i] = Pe2; g_acc[6][i] = Pe2x;
    }
}

// ---------------- samix / slerp ----------------
__global__ void samix_k(const float* __restrict__ sf, const float* __restrict__ points,
                        const float* __restrict__ lambp, const int* __restrict__ labels,
                        const int* __restrict__ mixed)
{
    int r = blockIdx.x * 8 + (threadIdx.x >> 5);
    int lane = threadIdx.x & 31;
    if (r >= NROW) return;
    int lr = labels[r & (BQ - 1)];
    int mi = mixed[r];
    int lp = labels[mi & (BQ - 1)];
    const float* corr = points + (size_t)lr * DIM;
    const float* perm = points + (size_t)lp * DIM;
    const float* s = sf + (size_t)r * DIM;
    float dcp = 0.f, dsc = 0.f, dsp = 0.f;
    for (int k = lane * 4; k < DIM; k += 128) {
        float4 cc = *(const float4*)(corr + k);
        float4 pp = *(const float4*)(perm + k);
        float4 vv = *(const float4*)(s + k);
        dcp += cc.x * pp.x + cc.y * pp.y + cc.z * pp.z + cc.w * pp.w;
        dsc += vv.x * cc.x + vv.y * cc.y + vv.z * cc.z + vv.w * cc.w;
        dsp += vv.x * pp.x + vv.y * pp.y + vv.z * pp.z + vv.w * pp.w;
    }
#pragma unroll
    for (int o = 16; o > 0; o >>= 1) {
        dcp += __shfl_xor_sync(0xffffffffu, dcp, o);
        dsc += __shfl_xor_sync(0xffffffffu, dsc, o);
        dsp += __shfl_xor_sync(0xffffffffu, dsp, o);
    }
    if (lane == 0) {
        float lamb = *lambp;
        float cost = fminf(1.f, fmaxf(-1.f, dcp));
        float theta = acosf(cost);
        float sval;
        if (theta < 1e-6f) {
            sval = dsc;
        } else {
            float st = sinf(theta);
            sval = (sinf(lamb * theta) / st) * dsc + (sinf((1.f - lamb) * theta) / st) * dsp;
        }
        float d = sval - 1.f;
        atomicAdd(&g_loss[1], 0.5f * d * d);
    }
}

// ---------------- finalize ----------------
__global__ void finalize_k(const int* __restrict__ labels,
                           const int* __restrict__ tlab, int ntl)
{
    int i = blockIdx.x * blockDim.x + threadIdx.x;
    int lane = threadIdx.x & 31;
    float val = 0.f;
    if (i < NROW) {
        float Dn = g_acc[0][i];
        float P0 = g_acc[1][i], P1 = g_acc[2][i], Pe = g_acc[3][i];
        float Pex = g_acc[4][i], Pe2 = g_acc[5][i], Pe2x = g_acc[6][i];
        float LD = logf(Dn);
        float inv = 1.f / Dn;
        float w0 = P0 - 2.f * Pe * inv + Pe2 * inv * inv;
        float wx = P1 - 2.f * Pex * inv + Pe2x * inv * inv;
        float S = wx - LD * w0;
        float pos = (P0 < 1e-6f) ? 1.f : P0;
        float mlpp = -S / pos;
        int li = labels[i & (BQ - 1)];
        bool curr = false;
        for (int k = 0; k < ntl; ++k) curr |= (tlab[k] == li);
        val = curr ? mlpp : 0.f;
    }
#pragma unroll
    for (int o = 16; o > 0; o >>= 1) val += __shfl_xor_sync(0xffffffffu, val, o);
    if (lane == 0) atomicAdd(&g_loss[0], val);
}

__global__ void combine_k(float* __restrict__ out)
{
    if (threadIdx.x == 0)
        out[0] = (g_loss[0] + g_loss[1]) * (1.0f / (float)NROW);
}

// ---------------- launch ----------------
extern "C" void kernel_launch(void* const* d_in, const int* in_sizes, int n_in,
                              void* d_out, int out_size)
{
    const float* features = (const float*)d_in[0];
    const float* samix    = (const float*)d_in[1];
    const float* points   = (const float*)d_in[2];
    const float* lamb     = (const float*)d_in[3];
    const int*   labels   = (const int*)d_in[4];
    const int*   tlab     = (const int*)d_in[5];
    const int*   mixed    = (const int*)d_in[6];
    const int*   prevp    = (n_in > 7) ? (const int*)d_in[7] : nullptr;
    int ntl = in_sizes[5];

    const int ntiles = NTILR * NTILC - (NTILR * (NTILR - 1)) / 2;  // 560

    init_k<<<(NROW + 255) / 256, 256>>>(labels);
    bucket_k<<<(BQ + 255) / 256, 256>>>(labels);
    prep_X<<<(XROWS * DIM / 4 + 255) / 256, 256>>>(features, points, prevp);
    pointsdot_k<<<NROW / 8, 256>>>(features, points);
    gemm_epi<<<ntiles, 256>>>(prevp);
    pos_k<<<NROW / 8, 256>>>();
    samix_k<<<NROW / 8, 256>>>(samix, points, lamb, labels, mixed);
    finalize_k<<<(NROW + 255) / 256, 256>>>(labels, tlab, ntl);
    combine_k<<<1, 32>>>((float*)d_out);
    (void)out_size;
}

// round 5
// speedup vs baseline: 1.8912x; 1.1582x over previous
#include <cuda_runtime.h>
#include <cuda_bf16.h>
#include <cstdint>

#define BQ    2048
#define DIM   1024
#define NROW  4096
#define XROWS 4224
#define NTILR 32
#define NTILC 33
#define TINV  14.285714285714285f
#define LOG2E 1.4426950408889634f
#define C1EXP (TINV * LOG2E)
#define BCAP  64

// ---------------- scratch (device globals; zero-initialized, self-cleaning) ----------------
__device__ __nv_bfloat16 g_X[(size_t)XROWS * DIM];
__device__ float g_pointsdot[NROW];
__device__ int   g_lab[NROW];
__device__ float g_acc[7][NROW];      // [0]=E  [1..6]=P0,P1,Pe,Pex,Pe2,Pe2x
__device__ float g_loss[2];
__device__ int   g_cnt[1000];
__device__ int   g_bucket[1000 * BCAP];

__device__ __forceinline__ float ex2f(float y)
{
    float r;
    asm("ex2.approx.ftz.f32 %0, %1;" : "=f"(r) : "f"(y));
    return r;
}

// ---------------- bucket + rep_labels (g_cnt zeroed by previous finalize / static init) ----
__global__ void bucket_k(const int* __restrict__ labels)
{
    int i = blockIdx.x * blockDim.x + threadIdx.x;
    if (i < NROW) g_lab[i] = labels[i & (BQ - 1)];
    if (i < BQ) {
        int lab = labels[i];
        int idx = atomicAdd(&g_cnt[lab], 1);
        if (idx < BCAP) g_bucket[lab * BCAP + idx] = i;
    }
}

// ---------------- X = [anchor(4096) ; prev_proto ; zeros], bf16 ----------------
__global__ void prep_X(const float* __restrict__ feats,
                       const float* __restrict__ points,
                       const int* __restrict__ prevp)
{
    const int PREV = prevp ? *prevp : 100;
    int idx = blockIdx.x * blockDim.x + threadIdx.x;
    int r = idx >> 8;
    int c = (idx & 255) << 2;
    if (r >= XROWS) return;
    float4 v = make_float4(0.f, 0.f, 0.f, 0.f);
    if (r < NROW) {
        const float* src = feats + ((r < BQ) ? (size_t)r * (2 * DIM)
                                             : (size_t)(r - BQ) * (2 * DIM) + DIM);
        v = *(const float4*)(src + c);
    } else if (r < NROW + PREV) {
        v = *(const float4*)(points + (size_t)(r - NROW) * DIM + c);
    }
    union { uint2 u; __nv_bfloat162 h[2]; } o;
    o.h[0] = __floats2bfloat162_rn(v.x, v.y);
    o.h[1] = __floats2bfloat162_rn(v.z, v.w);
    *(uint2*)(g_X + (size_t)r * DIM + c) = o.u;
}

// ---------------- diag replacement: anchor_i . points[label_i] / T (fp32 exact) ----------------
__global__ void pointsdot_k(const float* __restrict__ feats,
                            const float* __restrict__ points)
{
    int r = blockIdx.x * 8 + (threadIdx.x >> 5);
    int lane = threadIdx.x & 31;
    if (r >= NROW) return;
    const float* a = feats + ((r < BQ) ? (size_t)r * (2 * DIM)
                                       : (size_t)(r - BQ) * (2 * DIM) + DIM);
    const float* p = points + (size_t)g_lab[r] * DIM;
    float s = 0.f;
    for (int k = lane * 4; k < DIM; k += 128) {
        float4 av = *(const float4*)(a + k);
        float4 pv = *(const float4*)(p + k);
        s += av.x * pv.x + av.y * pv.y + av.z * pv.z + av.w * pv.w;
    }
#pragma unroll
    for (int o = 16; o > 0; o >>= 1) s += __shfl_xor_sync(0xffffffffu, s, o);
    if (lane == 0) g_pointsdot[r] = s * TINV;
}

// ---------------- symmetric GEMM (mma.sync) + denominator epilogue ----------------
// Tiles (r,c) with c>=r. K-chunk = 64 (4 k16 slices per barrier pair).
// Dynamic SMEM: As[2][128][72], Bs[2][128][72] bf16. Diag tiles reuse As for B.
#define ASTRIDE 72
#define ABUF    (128 * ASTRIDE)       // 9216 elements per buffer
#define SMEM_SZ (4 * ABUF * 2)        // 73728 bytes

__global__ __launch_bounds__(256, 2) void gemm_epi(const int* __restrict__ prevp)
{
    extern __shared__ __nv_bfloat16 sm[];   // [A0 A1 B0 B1]

    const int PREV  = prevp ? *prevp : 100;
    const int NCOLS = NROW + PREV;

    int t = blockIdx.x, r = 0;
    while (t >= NTILC - r) { t -= NTILC - r; ++r; }
    const int c = r + t;
    const int row0 = r * 128;
    const int col0 = c * 128;
    const int tile_type = (c == NTILC - 1) ? 2 : (c == r ? 0 : 1);
    const bool diag = (tile_type == 0);
    const int bbase = diag ? 0 : 2 * ABUF;   // element offset of the B storage

    const int tid = threadIdx.x;
    const int lane = tid & 31, wid = tid >> 5;
    const int wr = wid >> 1, wc = wid & 1;

    float acc[2][8][4];
#pragma unroll
    for (int a = 0; a < 2; a++)
#pragma unroll
        for (int b = 0; b < 8; b++)
#pragma unroll
            for (int q = 0; q < 4; q++) acc[a][b][q] = 0.f;

    auto issue = [&](int it, int buf) {
        int k0 = it * 64;
#pragma unroll
        for (int h = 0; h < 4; ++h) {
            int p = tid + h * 256;
            int rr = p >> 3, s = p & 7;
            const __nv_bfloat16* ga = g_X + (size_t)(row0 + rr) * DIM + k0 + s * 8;
            uint32_t sa = (uint32_t)__cvta_generic_to_shared(&sm[buf * ABUF + rr * ASTRIDE + s * 8]);
            asm volatile("cp.async.cg.shared.global [%0], [%1], 16;" :: "r"(sa), "l"(ga));
        }
        if (!diag) {
#pragma unroll
            for (int h = 0; h < 4; ++h) {
                int p = tid + h * 256;
                int rr = p >> 3, s = p & 7;
                const __nv_bfloat16* gb = g_X + (size_t)(col0 + rr) * DIM + k0 + s * 8;
                uint32_t sb = (uint32_t)__cvta_generic_to_shared(&sm[2 * ABUF + buf * ABUF + rr * ASTRIDE + s * 8]);
                asm volatile("cp.async.cg.shared.global [%0], [%1], 16;" :: "r"(sb), "l"(gb));
            }
        }
        asm volatile("cp.async.commit_group;");
    };

    issue(0, 0);
#pragma unroll 1
    for (int it = 0; it < 16; ++it) {
        int buf = it & 1;
        if (it < 15) {
            issue(it + 1, buf ^ 1);
            asm volatile("cp.async.wait_group 1;");
        } else {
            asm volatile("cp.async.wait_group 0;");
        }
        __syncthreads();
#pragma unroll
        for (int kk = 0; kk < 4; ++kk) {
            uint32_t a[2][4];
#pragma unroll
            for (int mt = 0; mt < 2; ++mt) {
                uint32_t addr = (uint32_t)__cvta_generic_to_shared(
                    &sm[buf * ABUF + (wr * 32 + mt * 16 + (lane & 15)) * ASTRIDE
                        + kk * 16 + ((lane >> 4) << 3)]);
                asm volatile("ldmatrix.sync.aligned.m8n8.x4.shared.b16 {%0,%1,%2,%3}, [%4];"
                             : "=r"(a[mt][0]), "=r"(a[mt][1]), "=r"(a[mt][2]), "=r"(a[mt][3])
                             : "r"(addr));
            }
            uint32_t b[8][2];
#pragma unroll
            for (int nt2 = 0; nt2 < 4; ++nt2) {
                int n_off = wc * 64 + nt2 * 16 + (lane & 7) + ((lane & 16) >> 1);
                int k_off = kk * 16 + (lane & 8);
                uint32_t addr = (uint32_t)__cvta_generic_to_shared(
                    &sm[bbase + buf * ABUF + n_off * ASTRIDE + k_off]);
                uint32_t r0, r1, r2, r3;
                asm volatile("ldmatrix.sync.aligned.m8n8.x4.shared.b16 {%0,%1,%2,%3}, [%4];"
                             : "=r"(r0), "=r"(r1), "=r"(r2), "=r"(r3) : "r"(addr));
                b[2 * nt2][0] = r0; b[2 * nt2][1] = r1;
                b[2 * nt2 + 1][0] = r2; b[2 * nt2 + 1][1] = r3;
            }
#pragma unroll
            for (int mt = 0; mt < 2; ++mt)
#pragma unroll
                for (int nt = 0; nt < 8; ++nt)
                    asm volatile("mma.sync.aligned.m16n8k16.row.col.f32.bf16.bf16.f32 "
                                 "{%0,%1,%2,%3},{%4,%5,%6,%7},{%8,%9},{%0,%1,%2,%3};"
                                 : "+f"(acc[mt][nt][0]), "+f"(acc[mt][nt][1]),
                                   "+f"(acc[mt][nt][2]), "+f"(acc[mt][nt][3])
                                 : "r"(a[mt][0]), "r"(a[mt][1]), "r"(a[mt][2]), "r"(a[mt][3]),
                                   "r"(b[nt][0]), "r"(b[nt][1]));
        }
        __syncthreads();
    }

    // -------- epilogue: denominator only --------
    float rowE[4] = {0.f, 0.f, 0.f, 0.f};
    float colE[16];
#pragma unroll
    for (int q = 0; q < 16; q++) colE[q] = 0.f;

    int irow[4];
#pragma unroll
    for (int rs = 0; rs < 4; rs++)
        irow[rs] = row0 + wr * 32 + (rs >> 1) * 16 + (rs & 1) * 8 + (lane >> 2);

#pragma unroll
    for (int mt = 0; mt < 2; ++mt)
#pragma unroll
        for (int nt = 0; nt < 8; ++nt)
#pragma unroll
            for (int q = 0; q < 4; ++q) {
                int rs = mt * 2 + (q >> 1);
                float e = ex2f(fmaf(acc[mt][nt][q], C1EXP, -C1EXP));
                if (tile_type != 1) {
                    int j = col0 + wc * 64 + nt * 8 + (lane & 3) * 2 + (q & 1);
                    if (tile_type == 2) { if (j >= NCOLS) e = 0.f; }
                    else                { if (j == irow[rs]) e = 0.f; }
                }
                rowE[rs] += e;
                colE[nt * 2 + (q & 1)] += e;
            }

#pragma unroll
    for (int rs = 0; rs < 4; rs++) {
        float v = rowE[rs];
        v += __shfl_xor_sync(0xffffffffu, v, 1);
        v += __shfl_xor_sync(0xffffffffu, v, 2);
        if ((lane & 3) == 0) atomicAdd(&g_acc[0][irow[rs]], v);
    }
    if (tile_type == 1) {
#pragma unroll
        for (int idx = 0; idx < 16; ++idx) {
            float v = colE[idx];
            v += __shfl_xor_sync(0xffffffffu, v, 4);
            v += __shfl_xor_sync(0xffffffffu, v, 8);
            v += __shfl_xor_sync(0xffffffffu, v, 16);
            if (lane < 4) {
                int j = col0 + wc * 64 + (idx >> 1) * 8 + lane * 2 + (idx & 1);
                atomicAdd(&g_acc[0][j], v);
            }
        }
    }
}

// ---------------- sparse positive pass + samix/slerp (merged, warp per row) ----------------
__global__ void pos_samix_k(const float* __restrict__ sf, const float* __restrict__ points,
                            const float* __restrict__ lambp, const int* __restrict__ labels,
                            const int* __restrict__ mixed)
{
    int i = blockIdx.x * 8 + (threadIdx.x >> 5);
    int lane = threadIdx.x & 31;
    if (i >= NROW) return;

    // ---- positives ----
    {
        int lab = g_lab[i];
        int cnt = g_cnt[lab];
        if (cnt > BCAP) cnt = BCAP;

        const uint2* xi = (const uint2*)(g_X + (size_t)i * DIM);
        float rif[32];
#pragma unroll
        for (int k = 0; k < 8; ++k) {
            uint2 u = xi[lane + 32 * k];
            float2 f0 = __bfloat1622float2(*(const __nv_bfloat162*)&u.x);
            float2 f1 = __bfloat1622float2(*(const __nv_bfloat162*)&u.y);
            rif[k * 4 + 0] = f0.x; rif[k * 4 + 1] = f0.y;
            rif[k * 4 + 2] = f1.x; rif[k * 4 + 3] = f1.y;
        }

        float P0 = 0.f, P1 = 0.f, Pe = 0.f, Pex = 0.f, Pe2 = 0.f, Pe2x = 0.f;
        for (int b = 0; b < cnt; ++b) {
            int base = g_bucket[lab * BCAP + b];
#pragma unroll
            for (int v = 0; v < 2; ++v) {
                int j = base + v * BQ;
                float x;
                if (j == i) {
                    x = g_pointsdot[i] - TINV;
                } else {
                    const uint2* xj = (const uint2*)(g_X + (size_t)j * DIM);
                    float d = 0.f;
#pragma unroll
                    for (int k = 0; k < 8; ++k) {
                        uint2 u = xj[lane + 32 * k];
                        float2 f0 = __bfloat1622float2(*(const __nv_bfloat162*)&u.x);
                        float2 f1 = __bfloat1622float2(*(const __nv_bfloat162*)&u.y);
                        d = fmaf(rif[k * 4 + 0], f0.x, d);
                        d = fmaf(rif[k * 4 + 1], f0.y, d);
                        d = fmaf(rif[k * 4 + 2], f1.x, d);
                        d = fmaf(rif[k * 4 + 3], f1.y, d);
                    }
#pragma unroll
                    for (int o = 16; o > 0; o >>= 1) d += __shfl_xor_sync(0xffffffffu, d, o);
                    x = fmaf(d, TINV, -TINV);
                }
                float e = ex2f(x * LOG2E);
                P0 += 1.f; P1 += x; Pe += e;
                Pex += e * x; Pe2 += e * e; Pe2x += e * e * x;
            }
        }
        if (lane == 0) {
            g_acc[1][i] = P0; g_acc[2][i] = P1; g_acc[3][i] = Pe;
            g_acc[4][i] = Pex; g_acc[5][i] = Pe2; g_acc[6][i] = Pe2x;
        }
    }

    // ---- samix / slerp ----
    {
        int lr = labels[i & (BQ - 1)];
        int mi = mixed[i];
        int lp = labels[mi & (BQ - 1)];
        const float* corr = points + (size_t)lr * DIM;
        const float* perm = points + (size_t)lp * DIM;
        const float* s = sf + (size_t)i * DIM;
        float dcp = 0.f, dsc = 0.f, dsp = 0.f;
        for (int k = lane * 4; k < DIM; k += 128) {
            float4 cc = *(const float4*)(corr + k);
            float4 pp = *(const float4*)(perm + k);
            float4 vv = *(const float4*)(s + k);
            dcp += cc.x * pp.x + cc.y * pp.y + cc.z * pp.z + cc.w * pp.w;
            dsc += vv.x * cc.x + vv.y * cc.y + vv.z * cc.z + vv.w * cc.w;
            dsp += vv.x * pp.x + vv.y * pp.y + vv.z * pp.z + vv.w * pp.w;
        }
#pragma unroll
        for (int o = 16; o > 0; o >>= 1) {
            dcp += __shfl_xor_sync(0xffffffffu, dcp, o);
            dsc += __shfl_xor_sync(0xffffffffu, dsc, o);
            dsp += __shfl_xor_sync(0xffffffffu, dsp, o);
        }
        if (lane == 0) {
            float lamb = *lambp;
            float cost = fminf(1.f, fmaxf(-1.f, dcp));
            float theta = acosf(cost);
            float sval;
            if (theta < 1e-6f) {
                sval = dsc;
            } else {
                float st = sinf(theta);
                sval = (sinf(lamb * theta) / st) * dsc + (sinf((1.f - lamb) * theta) / st) * dsp;
            }
            float d = sval - 1.f;
            atomicAdd(&g_loss[1], 0.5f * d * d);
        }
    }
}

// ---------------- finalize (+ cleanup for next replay) ----------------
__global__ void finalize_k(const int* __restrict__ labels,
                           const int* __restrict__ tlab, int ntl)
{
    int i = blockIdx.x * blockDim.x + threadIdx.x;
    int lane = threadIdx.x & 31;
    float val = 0.f;
    if (i < NROW) {
        float Dn = g_acc[0][i];
        float P0 = g_acc[1][i], P1 = g_acc[2][i], Pe = g_acc[3][i];
        float Pex = g_acc[4][i], Pe2 = g_acc[5][i], Pe2x = g_acc[6][i];
        float LD = logf(Dn);
        float inv = 1.f / Dn;
        float w0 = P0 - 2.f * Pe * inv + Pe2 * inv * inv;
        float wx = P1 - 2.f * Pex * inv + Pe2x * inv * inv;
        float S = wx - LD * w0;
        float pos = (P0 < 1e-6f) ? 1.f : P0;
        float mlpp = -S / pos;
        int li = labels[i & (BQ - 1)];
        bool curr = false;
        for (int k = 0; k < ntl; ++k) curr |= (tlab[k] == li);
        val = curr ? mlpp : 0.f;
        g_acc[0][i] = 0.f;          // cleanup for next replay
    }
    if (i < 1000) g_cnt[i] = 0;     // cleanup for next replay
#pragma unroll
    for (int o = 16; o > 0; o >>= 1) val += __shfl_xor_sync(0xffffffffu, val, o);
    if (lane == 0) atomicAdd(&g_loss[0], val);
}

__global__ void combine_k(float* __restrict__ out)
{
    if (threadIdx.x == 0) {
        out[0] = (g_loss[0] + g_loss[1]) * (1.0f / (float)NROW);
        g_loss[0] = 0.f;            // cleanup for next replay
        g_loss[1] = 0.f;
    }
}

// ---------------- launch ----------------
extern "C" void kernel_launch(void* const* d_in, const int* in_sizes, int n_in,
                              void* d_out, int out_size)
{
    const float* features = (const float*)d_in[0];
    const float* samix    = (const float*)d_in[1];
    const float* points   = (const float*)d_in[2];
    const float* lamb     = (const float*)d_in[3];
    const int*   labels   = (const int*)d_in[4];
    const int*   tlab     = (const int*)d_in[5];
    const int*   mixed    = (const int*)d_in[6];
    const int*   prevp    = (n_in > 7) ? (const int*)d_in[7] : nullptr;
    int ntl = in_sizes[5];

    static bool attr_set = false;
    if (!attr_set) {
        cudaFuncSetAttribute(gemm_epi, cudaFuncAttributeMaxDynamicSharedMemorySize, SMEM_SZ);
        attr_set = true;
    }

    const int ntiles = NTILR * NTILC - (NTILR * (NTILR - 1)) / 2;  // 560

    bucket_k<<<(NROW + 255) / 256, 256>>>(labels);
    prep_X<<<(XROWS * DIM / 4 + 255) / 256, 256>>>(features, points, prevp);
    pointsdot_k<<<NROW / 8, 256>>>(features, points);
    gemm_epi<<<ntiles, 256, SMEM_SZ>>>(prevp);
    pos_samix_k<<<NROW / 8, 256>>>(samix, points, lamb, labels, mixed);
    finalize_k<<<(NROW + 255) / 256, 256>>>(labels, tlab, ntl);
    combine_k<<<1, 32>>>((float*)d_out);
    (void)out_size;
}

// round 6
// speedup vs baseline: 2.5263x; 1.3358x over previous
#include <cuda_runtime.h>
#include <cuda_bf16.h>
#include <cstdint>

#define BQ    2048
#define DIM   1024
#define NROW  4096
#define XROWS 4224
#define NTILR 32
#define NTILC 33
#define TINV  14.285714285714285f
#define LOG2E 1.4426950408889634f
#define C1EXP (TINV * LOG2E)
#define BCAP  64

// ---------------- scratch (device globals; zero-initialized, self-cleaning) ----------------
__device__ __nv_bfloat16 g_X[(size_t)XROWS * DIM];
__device__ int   g_lab[NROW];
__device__ float g_acc[7][NROW];      // [0]=E  [1..6]=P0,P1,Pe,Pex,Pe2,Pe2x
__device__ float g_loss2;             // samix sum
__device__ int   g_cnt[1000];
__device__ int   g_bucket[1000 * BCAP];
__device__ unsigned char g_tmask[1000];

__device__ __forceinline__ float ex2f(float y)
{
    float r;
    asm("ex2.approx.ftz.f32 %0, %1;" : "=f"(r) : "f"(y));
    return r;
}

// ---------------- prep: X(bf16) + rep_labels + buckets + target mask ----------------
__global__ void prep_all(const float* __restrict__ feats,
                         const float* __restrict__ points,
                         const int* __restrict__ labels,
                         const int* __restrict__ tlab, int ntl,
                         const int* __restrict__ prevp)
{
    const int PREV = prevp ? *prevp : 100;
    int idx = blockIdx.x * blockDim.x + threadIdx.x;

    if (idx < NROW) g_lab[idx] = labels[idx & (BQ - 1)];
    if (idx < BQ) {
        int lab = labels[idx];
        int p = atomicAdd(&g_cnt[lab], 1);
        if (p < BCAP) g_bucket[lab * BCAP + p] = idx;
    }
    if (idx < ntl) g_tmask[tlab[idx]] = 1;

    int r = idx >> 8;
    int c = (idx & 255) << 2;
    if (r >= XROWS) return;
    float4 v = make_float4(0.f, 0.f, 0.f, 0.f);
    if (r < NROW) {
        const float* src = feats + ((r < BQ) ? (size_t)r * (2 * DIM)
                                             : (size_t)(r - BQ) * (2 * DIM) + DIM);
        v = *(const float4*)(src + c);
    } else if (r < NROW + PREV) {
        v = *(const float4*)(points + (size_t)(r - NROW) * DIM + c);
    }
    union { uint2 u; __nv_bfloat162 h[2]; } o;
    o.h[0] = __floats2bfloat162_rn(v.x, v.y);
    o.h[1] = __floats2bfloat162_rn(v.z, v.w);
    *(uint2*)(g_X + (size_t)r * DIM + c) = o.u;
}

// ---------------- symmetric GEMM (mma.sync) + denominator epilogue ----------------
// Tiles (r,c), c>=r. 3-stage cp.async pipeline, one __syncthreads per K-iter.
// XOR-swizzled smem, no pad: 6 buffers x 16KB = 96KB dynamic.
#define ABUF    (128 * 64)            // elements per buffer (16KB)
#define SMEM_SZ (6 * ABUF * 2)        // 98304 bytes

__global__ __launch_bounds__(256, 2) void gemm_epi(const int* __restrict__ prevp)
{
    extern __shared__ __nv_bfloat16 sm[];   // [A0 A1 A2 B0 B1 B2]

    const int PREV  = prevp ? *prevp : 100;
    const int NCOLS = NROW + PREV;

    int t = blockIdx.x, r = 0;
    while (t >= NTILC - r) { t -= NTILC - r; ++r; }
    const int c = r + t;
    const int row0 = r * 128;
    const int col0 = c * 128;
    const int tile_type = (c == NTILC - 1) ? 2 : (c == r ? 0 : 1);
    const bool diag = (tile_type == 0);
    const int bbase = diag ? 0 : 3 * ABUF;

    const int tid = threadIdx.x;
    const int lane = tid & 31, wid = tid >> 5;
    const int wr = wid >> 1, wc = wid & 1;

    float acc[2][8][4];
#pragma unroll
    for (int a = 0; a < 2; a++)
#pragma unroll
        for (int b = 0; b < 8; b++)
#pragma unroll
            for (int q = 0; q < 4; q++) acc[a][b][q] = 0.f;

    auto issue = [&](int it, int buf) {
        int k0 = it * 64;
#pragma unroll
        for (int h = 0; h < 4; ++h) {
            int p = tid + h * 256;
            int rr = p >> 3, s = p & 7;
            const __nv_bfloat16* ga = g_X + (size_t)(row0 + rr) * DIM + k0 + s * 8;
            uint32_t sa = (uint32_t)__cvta_generic_to_shared(
                &sm[buf * ABUF + rr * 64 + ((s ^ (rr & 7)) << 3)]);
            asm volatile("cp.async.cg.shared.global [%0], [%1], 16;" :: "r"(sa), "l"(ga));
        }
        if (!diag) {
#pragma unroll
            for (int h = 0; h < 4; ++h) {
                int p = tid + h * 256;
                int rr = p >> 3, s = p & 7;
                const __nv_bfloat16* gb = g_X + (size_t)(col0 + rr) * DIM + k0 + s * 8;
                uint32_t sb = (uint32_t)__cvta_generic_to_shared(
                    &sm[3 * ABUF + buf * ABUF + rr * 64 + ((s ^ (rr & 7)) << 3)]);
                asm volatile("cp.async.cg.shared.global [%0], [%1], 16;" :: "r"(sb), "l"(gb));
            }
        }
        asm volatile("cp.async.commit_group;");
    };

    issue(0, 0);
    issue(1, 1);

    int bufs = 0;          // rotates 0,1,2
#pragma unroll 1
    for (int it = 0; it < 16; ++it) {
        const int buf = bufs;
        bufs = (bufs == 2) ? 0 : bufs + 1;
        if (it < 15) asm volatile("cp.async.wait_group 1;");
        else         asm volatile("cp.async.wait_group 0;");
        __syncthreads();
        if (it + 2 < 16) {
            int nb = buf + 2; if (nb >= 3) nb -= 3;
            issue(it + 2, nb);
        }
#pragma unroll
        for (int kk = 0; kk < 4; ++kk) {
            uint32_t a[2][4];
#pragma unroll
            for (int mt = 0; mt < 2; ++mt) {
                int row = wr * 32 + mt * 16 + (lane & 15);
                int ch  = kk * 2 + (lane >> 4);
                uint32_t addr = (uint32_t)__cvta_generic_to_shared(
                    &sm[buf * ABUF + row * 64 + ((ch ^ (row & 7)) << 3)]);
                asm volatile("ldmatrix.sync.aligned.m8n8.x4.shared.b16 {%0,%1,%2,%3}, [%4];"
                             : "=r"(a[mt][0]), "=r"(a[mt][1]), "=r"(a[mt][2]), "=r"(a[mt][3])
                             : "r"(addr));
            }
            uint32_t b[8][2];
#pragma unroll
            for (int nt2 = 0; nt2 < 4; ++nt2) {
                int row = wc * 64 + nt2 * 16 + (lane & 7) + ((lane & 16) >> 1);
                int ch  = kk * 2 + ((lane >> 3) & 1);
                uint32_t addr = (uint32_t)__cvta_generic_to_shared(
                    &sm[bbase + buf * ABUF + row * 64 + ((ch ^ (row & 7)) << 3)]);
                uint32_t r0, r1, r2, r3;
                asm volatile("ldmatrix.sync.aligned.m8n8.x4.shared.b16 {%0,%1,%2,%3}, [%4];"
                             : "=r"(r0), "=r"(r1), "=r"(r2), "=r"(r3) : "r"(addr));
                b[2 * nt2][0] = r0; b[2 * nt2][1] = r1;
                b[2 * nt2 + 1][0] = r2; b[2 * nt2 + 1][1] = r3;
            }
#pragma unroll
            for (int mt = 0; mt < 2; ++mt)
#pragma unroll
                for (int nt = 0; nt < 8; ++nt)
                    asm volatile("mma.sync.aligned.m16n8k16.row.col.f32.bf16.bf16.f32 "
                                 "{%0,%1,%2,%3},{%4,%5,%6,%7},{%8,%9},{%0,%1,%2,%3};"
                                 : "+f"(acc[mt][nt][0]), "+f"(acc[mt][nt][1]),
                                   "+f"(acc[mt][nt][2]), "+f"(acc[mt][nt][3])
                                 : "r"(a[mt][0]), "r"(a[mt][1]), "r"(a[mt][2]), "r"(a[mt][3]),
                                   "r"(b[nt][0]), "r"(b[nt][1]));
        }
    }

    // -------- epilogue: denominator only --------
    float rowE[4] = {0.f, 0.f, 0.f, 0.f};
    float colE[16];
#pragma unroll
    for (int q = 0; q < 16; q++) colE[q] = 0.f;

    int irow[4];
#pragma unroll
    for (int rs = 0; rs < 4; rs++)
        irow[rs] = row0 + wr * 32 + (rs >> 1) * 16 + (rs & 1) * 8 + (lane >> 2);

#pragma unroll
    for (int mt = 0; mt < 2; ++mt)
#pragma unroll
        for (int nt = 0; nt < 8; ++nt)
#pragma unroll
            for (int q = 0; q < 4; ++q) {
                int rs = mt * 2 + (q >> 1);
                float e = ex2f(fmaf(acc[mt][nt][q], C1EXP, -C1EXP));
                if (tile_type != 1) {
                    int j = col0 + wc * 64 + nt * 8 + (lane & 3) * 2 + (q & 1);
                    if (tile_type == 2) { if (j >= NCOLS) e = 0.f; }
                    else                { if (j == irow[rs]) e = 0.f; }
                }
                rowE[rs] += e;
                colE[nt * 2 + (q & 1)] += e;
            }

#pragma unroll
    for (int rs = 0; rs < 4; rs++) {
        float v = rowE[rs];
        v += __shfl_xor_sync(0xffffffffu, v, 1);
        v += __shfl_xor_sync(0xffffffffu, v, 2);
        if ((lane & 3) == 0) atomicAdd(&g_acc[0][irow[rs]], v);
    }
    if (tile_type == 1) {
#pragma unroll
        for (int idx = 0; idx < 16; ++idx) {
            float v = colE[idx];
            v += __shfl_xor_sync(0xffffffffu, v, 4);
            v += __shfl_xor_sync(0xffffffffu, v, 8);
            v += __shfl_xor_sync(0xffffffffu, v, 16);
            if (lane < 4) {
                int j = col0 + wc * 64 + (idx >> 1) * 8 + lane * 2 + (idx & 1);
                atomicAdd(&g_acc[0][j], v);
            }
        }
    }
}

// ---------------- positives (with inlined points_dot) + samix/slerp, warp per row ----------------
__global__ void pos_samix_k(const float* __restrict__ feats,
                            const float* __restrict__ sf, const float* __restrict__ points,
                            const float* __restrict__ lambp, const int* __restrict__ labels,
                            const int* __restrict__ mixed)
{
    int i = blockIdx.x * 8 + (threadIdx.x >> 5);
    int lane = threadIdx.x & 31;
    if (i >= NROW) return;
    int lab = g_lab[i];

    // ---- points_dot (fp32 exact, same summation order as before) ----
    float xself;
    {
        const float* a = feats + ((i < BQ) ? (size_t)i * (2 * DIM)
                                           : (size_t)(i - BQ) * (2 * DIM) + DIM);
        const float* p = points + (size_t)lab * DIM;
        float s = 0.f;
        for (int k = lane * 4; k < DIM; k += 128) {
            float4 av = *(const float4*)(a + k);
            float4 pv = *(const float4*)(p + k);
            s += av.x * pv.x + av.y * pv.y + av.z * pv.z + av.w * pv.w;
        }
#pragma unroll
        for (int o = 16; o > 0; o >>= 1) s += __shfl_xor_sync(0xffffffffu, s, o);
        xself = s * TINV - TINV;
    }

    // ---- positives ----
    {
        int cnt = g_cnt[lab];
        if (cnt > BCAP) cnt = BCAP;

        const uint2* xi = (const uint2*)(g_X + (size_t)i * DIM);
        float rif[32];
#pragma unroll
        for (int k = 0; k < 8; ++k) {
            uint2 u = xi[lane + 32 * k];
            float2 f0 = __bfloat1622float2(*(const __nv_bfloat162*)&u.x);
            float2 f1 = __bfloat1622float2(*(const __nv_bfloat162*)&u.y);
            rif[k * 4 + 0] = f0.x; rif[k * 4 + 1] = f0.y;
            rif[k * 4 + 2] = f1.x; rif[k * 4 + 3] = f1.y;
        }

        float P0 = 0.f, P1 = 0.f, Pe = 0.f, Pex = 0.f, Pe2 = 0.f, Pe2x = 0.f;
        for (int b = 0; b < cnt; ++b) {
            int base = g_bucket[lab * BCAP + b];
#pragma unroll
            for (int v = 0; v < 2; ++v) {
                int j = base + v * BQ;
                float x;
                if (j == i) {
                    x = xself;
                } else {
                    const uint2* xj = (const uint2*)(g_X + (size_t)j * DIM);
                    float d = 0.f;
#pragma unroll
                    for (int k = 0; k < 8; ++k) {
                        uint2 u = xj[lane + 32 * k];
                        float2 f0 = __bfloat1622float2(*(const __nv_bfloat162*)&u.x);
                        float2 f1 = __bfloat1622float2(*(const __nv_bfloat162*)&u.y);
                        d = fmaf(rif[k * 4 + 0], f0.x, d);
                        d = fmaf(rif[k * 4 + 1], f0.y, d);
                        d = fmaf(rif[k * 4 + 2], f1.x, d);
                        d = fmaf(rif[k * 4 + 3], f1.y, d);
                    }
#pragma unroll
                    for (int o = 16; o > 0; o >>= 1) d += __shfl_xor_sync(0xffffffffu, d, o);
                    x = fmaf(d, TINV, -TINV);
                }
                float e = ex2f(x * LOG2E);
                P0 += 1.f; P1 += x; Pe += e;
                Pex += e * x; Pe2 += e * e; Pe2x += e * e * x;
            }
        }
        if (lane == 0) {
            g_acc[1][i] = P0; g_acc[2][i] = P1; g_acc[3][i] = Pe;
            g_acc[4][i] = Pex; g_acc[5][i] = Pe2; g_acc[6][i] = Pe2x;
        }
    }

    // ---- samix / slerp ----
    {
        int lr = labels[i & (BQ - 1)];
        int mi = mixed[i];
        int lp = labels[mi & (BQ - 1)];
        const float* corr = points + (size_t)lr * DIM;
        const float* perm = points + (size_t)lp * DIM;
        const float* s = sf + (size_t)i * DIM;
        float dcp = 0.f, dsc = 0.f, dsp = 0.f;
        for (int k = lane * 4; k < DIM; k += 128) {
            float4 cc = *(const float4*)(corr + k);
            float4 pp = *(const float4*)(perm + k);
            float4 vv = *(const float4*)(s + k);
            dcp += cc.x * pp.x + cc.y * pp.y + cc.z * pp.z + cc.w * pp.w;
            dsc += vv.x * cc.x + vv.y * cc.y + vv.z * cc.z + vv.w * cc.w;
            dsp += vv.x * pp.x + vv.y * pp.y + vv.z * pp.z + vv.w * pp.w;
        }
#pragma unroll
        for (int o = 16; o > 0; o >>= 1) {
            dcp += __shfl_xor_sync(0xffffffffu, dcp, o);
            dsc += __shfl_xor_sync(0xffffffffu, dsc, o);
            dsp += __shfl_xor_sync(0xffffffffu, dsp, o);
        }
        if (lane == 0) {
            float lamb = *lambp;
            float cost = fminf(1.f, fmaxf(-1.f, dcp));
            float theta = acosf(cost);
            float sval;
            if (theta < 1e-6f) {
                sval = dsc;
            } else {
                float st = sinf(theta);
                sval = (sinf(lamb * theta) / st) * dsc + (sinf((1.f - lamb) * theta) / st) * dsp;
            }
            float d = sval - 1.f;
            atomicAdd(&g_loss2, 0.5f * d * d);
        }
    }
}

// ---------------- finalize + combine (single block) + cleanup ----------------
__global__ void finalize_k(float* __restrict__ out)
{
    __shared__ float red[32];
    const int tid = threadIdx.x;
    const int lane = tid & 31, wid = tid >> 5;

    float val = 0.f;
    for (int i = tid; i < NROW; i += 1024) {
        float Dn = g_acc[0][i];
        float P0 = g_acc[1][i], P1 = g_acc[2][i], Pe = g_acc[3][i];
        float Pex = g_acc[4][i], Pe2 = g_acc[5][i], Pe2x = g_acc[6][i];
        float LD = logf(Dn);
        float inv = 1.f / Dn;
        float w0 = P0 - 2.f * Pe * inv + Pe2 * inv * inv;
        float wx = P1 - 2.f * Pex * inv + Pe2x * inv * inv;
        float S = wx - LD * w0;
        float pos = (P0 < 1e-6f) ? 1.f : P0;
        float mlpp = -S / pos;
        val += g_tmask[g_lab[i]] ? mlpp : 0.f;
        g_acc[0][i] = 0.f;                     // cleanup for next replay
    }
    __syncthreads();                           // all g_tmask reads done
    for (int i = tid; i < 1000; i += 1024) { g_cnt[i] = 0; g_tmask[i] = 0; }

#pragma unroll
    for (int o = 16; o > 0; o >>= 1) val += __shfl_xor_sync(0xffffffffu, val, o);
    if (lane == 0) red[wid] = val;
    __syncthreads();
    if (wid == 0) {
        float v = (lane < 32) ? red[lane] : 0.f;
#pragma unroll
        for (int o = 16; o > 0; o >>= 1) v += __shfl_xor_sync(0xffffffffu, v, o);
        if (lane == 0) {
            out[0] = (v + g_loss2) * (1.0f / (float)NROW);
            g_loss2 = 0.f;                     // cleanup for next replay
        }
    }
}

// ---------------- launch ----------------
extern "C" void kernel_launch(void* const* d_in, const int* in_sizes, int n_in,
                              void* d_out, int out_size)
{
    const float* features = (const float*)d_in[0];
    const float* samix    = (const float*)d_in[1];
    const float* points   = (const float*)d_in[2];
    const float* lamb     = (const float*)d_in[3];
    const int*   labels   = (const int*)d_in[4];
    const int*   tlab     = (const int*)d_in[5];
    const int*   mixed    = (const int*)d_in[6];
    const int*   prevp    = (n_in > 7) ? (const int*)d_in[7] : nullptr;
    int ntl = in_sizes[5];

    static bool attr_set = false;
    if (!attr_set) {
        cudaFuncSetAttribute(gemm_epi, cudaFuncAttributeMaxDynamicSharedMemorySize, SMEM_SZ);
        attr_set = true;
    }

    const int ntiles = NTILR * NTILC - (NTILR * (NTILR - 1)) / 2;  // 560

    prep_all<<<(XROWS * DIM / 4 + 255) / 256, 256>>>(features, points, labels, tlab, ntl, prevp);
    gemm_epi<<<ntiles, 256, SMEM_SZ>>>(prevp);
    pos_samix_k<<<NROW / 8, 256>>>(features, samix, points, lamb, labels, mixed);
    finalize_k<<<1, 1024>>>((float*)d_out);
    (void)out_size;
}

// round 7
// speedup vs baseline: 2.5519x; 1.0101x over previous
#include <cuda_runtime.h>
#include <cuda_bf16.h>
#include <cstdint>

#define BQ    2048
#define DIM   1024
#define NROW  4096
#define XROWS 4224
#define NTILR 32
#define NTILC 33
#define GTILES 560            // triangular gemm tiles
#define PBLKS  512            // pos/samix blocks (8 warps -> 8 rows each)
#define TINV  14.285714285714285f
#define LOG2E 1.4426950408889634f
#define LN2F  0.6931471805599453f
#define C1EXP (TINV * LOG2E)
#define BCAP  64

// ---------------- scratch (device globals; zero-initialized, self-cleaning) ----------------
__device__ __nv_bfloat16 g_X[(size_t)XROWS * DIM];
__device__ int   g_lab[NROW];
__device__ float g_acc[7][NROW];      // [0]=E  [1..6]=P0,P1,Pe,Pex,Pe2,Pe2x
__device__ float g_loss2;             // samix sum
__device__ int   g_cnt[1000];
__device__ int   g_bucket[1000 * BCAP];
__device__ unsigned char g_tmask[1000];

__device__ __forceinline__ float ex2f(float y)
{
    float r;
    asm("ex2.approx.ftz.f32 %0, %1;" : "=f"(r) : "f"(y));
    return r;
}
__device__ __forceinline__ float lg2f(float y)
{
    float r;
    asm("lg2.approx.ftz.f32 %0, %1;" : "=f"(r) : "f"(y));
    return r;
}

// ---------------- prep: X(bf16) + rep_labels + buckets + target mask ----------------
__global__ void prep_all(const float* __restrict__ feats,
                         const float* __restrict__ points,
                         const int* __restrict__ labels,
                         const int* __restrict__ tlab, int ntl,
                         const int* __restrict__ prevp)
{
    const int PREV = prevp ? *prevp : 100;
    int idx = blockIdx.x * blockDim.x + threadIdx.x;

    if (idx < NROW) g_lab[idx] = labels[idx & (BQ - 1)];
    if (idx < BQ) {
        int lab = labels[idx];
        int p = atomicAdd(&g_cnt[lab], 1);
        if (p < BCAP) g_bucket[lab * BCAP + p] = idx;
    }
    if (idx < ntl) g_tmask[tlab[idx]] = 1;

    int r = idx >> 8;
    int c = (idx & 255) << 2;
    if (r >= XROWS) return;
    float4 v = make_float4(0.f, 0.f, 0.f, 0.f);
    if (r < NROW) {
        const float* src = feats + ((r < BQ) ? (size_t)r * (2 * DIM)
                                             : (size_t)(r - BQ) * (2 * DIM) + DIM);
        v = *(const float4*)(src + c);
    } else if (r < NROW + PREV) {
        v = *(const float4*)(points + (size_t)(r - NROW) * DIM + c);
    }
    union { uint2 u; __nv_bfloat162 h[2]; } o;
    o.h[0] = __floats2bfloat162_rn(v.x, v.y);
    o.h[1] = __floats2bfloat162_rn(v.z, v.w);
    *(uint2*)(g_X + (size_t)r * DIM + c) = o.u;
}

// ---------------- merged: symmetric GEMM tiles (blocks 0..559) + pos/samix (560..1071) ----
#define ABUF    (128 * 64)            // elements per buffer (16KB)
#define SMEM_SZ (6 * ABUF * 2)        // 98304 bytes

__global__ __launch_bounds__(256, 2) void gemm_pos_k(
    const int* __restrict__ prevp,
    const float* __restrict__ feats,
    const float* __restrict__ sf, const float* __restrict__ points,
    const float* __restrict__ lambp, const int* __restrict__ labels,
    const int* __restrict__ mixed)
{
    extern __shared__ __nv_bfloat16 sm[];   // [A0 A1 A2 B0 B1 B2]

    const int tid = threadIdx.x;
    const int lane = tid & 31, wid = tid >> 5;

    // =================== pos / samix path ===================
    if (blockIdx.x >= GTILES) {
        int i = (blockIdx.x - GTILES) * 8 + wid;
        if (i >= NROW) return;
        int lab = g_lab[i];

        // ---- points_dot (fp32 exact) ----
        float xself;
        {
            const float* a = feats + ((i < BQ) ? (size_t)i * (2 * DIM)
                                               : (size_t)(i - BQ) * (2 * DIM) + DIM);
            const float* p = points + (size_t)lab * DIM;
            float s = 0.f;
            for (int k = lane * 4; k < DIM; k += 128) {
                float4 av = *(const float4*)(a + k);
                float4 pv = *(const float4*)(p + k);
                s += av.x * pv.x + av.y * pv.y + av.z * pv.z + av.w * pv.w;
            }
#pragma unroll
            for (int o = 16; o > 0; o >>= 1) s += __shfl_xor_sync(0xffffffffu, s, o);
            xself = s * TINV - TINV;
        }

        // ---- positives ----
        {
            int cnt = g_cnt[lab];
            if (cnt > BCAP) cnt = BCAP;

            const uint2* xi = (const uint2*)(g_X + (size_t)i * DIM);
            float rif[32];
#pragma unroll
            for (int k = 0; k < 8; ++k) {
                uint2 u = xi[lane + 32 * k];
                float2 f0 = __bfloat1622float2(*(const __nv_bfloat162*)&u.x);
                float2 f1 = __bfloat1622float2(*(const __nv_bfloat162*)&u.y);
                rif[k * 4 + 0] = f0.x; rif[k * 4 + 1] = f0.y;
                rif[k * 4 + 2] = f1.x; rif[k * 4 + 3] = f1.y;
            }

            float P0 = 0.f, P1 = 0.f, Pe = 0.f, Pex = 0.f, Pe2 = 0.f, Pe2x = 0.f;
            for (int b = 0; b < cnt; ++b) {
                int base = g_bucket[lab * BCAP + b];
#pragma unroll
                for (int v = 0; v < 2; ++v) {
                    int j = base + v * BQ;
                    float x;
                    if (j == i) {
                        x = xself;
                    } else {
                        const uint2* xj = (const uint2*)(g_X + (size_t)j * DIM);
                        float d = 0.f;
#pragma unroll
                        for (int k = 0; k < 8; ++k) {
                            uint2 u = xj[lane + 32 * k];
                            float2 f0 = __bfloat1622float2(*(const __nv_bfloat162*)&u.x);
                            float2 f1 = __bfloat1622float2(*(const __nv_bfloat162*)&u.y);
                            d = fmaf(rif[k * 4 + 0], f0.x, d);
                            d = fmaf(rif[k * 4 + 1], f0.y, d);
                            d = fmaf(rif[k * 4 + 2], f1.x, d);
                            d = fmaf(rif[k * 4 + 3], f1.y, d);
                        }
#pragma unroll
                        for (int o = 16; o > 0; o >>= 1) d += __shfl_xor_sync(0xffffffffu, d, o);
                        x = fmaf(d, TINV, -TINV);
                    }
                    float e = ex2f(x * LOG2E);
                    P0 += 1.f; P1 += x; Pe += e;
                    Pex += e * x; Pe2 += e * e; Pe2x += e * e * x;
                }
            }
            if (lane == 0) {
                g_acc[1][i] = P0; g_acc[2][i] = P1; g_acc[3][i] = Pe;
                g_acc[4][i] = Pex; g_acc[5][i] = Pe2; g_acc[6][i] = Pe2x;
            }
        }

        // ---- samix / slerp ----
        {
            int lr = labels[i & (BQ - 1)];
            int mi = mixed[i];
            int lp = labels[mi & (BQ - 1)];
            const float* corr = points + (size_t)lr * DIM;
            const float* perm = points + (size_t)lp * DIM;
            const float* s = sf + (size_t)i * DIM;
            float dcp = 0.f, dsc = 0.f, dsp = 0.f;
            for (int k = lane * 4; k < DIM; k += 128) {
                float4 cc = *(const float4*)(corr + k);
                float4 pp = *(const float4*)(perm + k);
                float4 vv = *(const float4*)(s + k);
                dcp += cc.x * pp.x + cc.y * pp.y + cc.z * pp.z + cc.w * pp.w;
                dsc += vv.x * cc.x + vv.y * cc.y + vv.z * cc.z + vv.w * cc.w;
                dsp += vv.x * pp.x + vv.y * pp.y + vv.z * pp.z + vv.w * pp.w;
            }
#pragma unroll
            for (int o = 16; o > 0; o >>= 1) {
                dcp += __shfl_xor_sync(0xffffffffu, dcp, o);
                dsc += __shfl_xor_sync(0xffffffffu, dsc, o);
                dsp += __shfl_xor_sync(0xffffffffu, dsp, o);
            }
            if (lane == 0) {
                float lamb = *lambp;
                float cost = fminf(1.f, fmaxf(-1.f, dcp));
                float theta = acosf(cost);
                float sval;
                if (theta < 1e-6f) {
                    sval = dsc;
                } else {
                    float st = sinf(theta);
                    sval = (sinf(lamb * theta) / st) * dsc + (sinf((1.f - lamb) * theta) / st) * dsp;
                }
                float d = sval - 1.f;
                atomicAdd(&g_loss2, 0.5f * d * d);
            }
        }
        return;
    }

    // =================== GEMM tile path ===================
    const int PREV  = prevp ? *prevp : 100;
    const int NCOLS = NROW + PREV;

    int t = blockIdx.x, r = 0;
    while (t >= NTILC - r) { t -= NTILC - r; ++r; }
    const int c = r + t;
    const int row0 = r * 128;
    const int col0 = c * 128;
    const int tile_type = (c == NTILC - 1) ? 2 : (c == r ? 0 : 1);
    const bool diag = (tile_type == 0);
    const int bbase = diag ? 0 : 3 * ABUF;

    const int wr = wid >> 1, wc = wid & 1;

    float acc[2][8][4];
#pragma unroll
    for (int a = 0; a < 2; a++)
#pragma unroll
        for (int b = 0; b < 8; b++)
#pragma unroll
            for (int q = 0; q < 4; q++) acc[a][b][q] = 0.f;

    auto issue = [&](int it, int buf) {
        int k0 = it * 64;
#pragma unroll
        for (int h = 0; h < 4; ++h) {
            int p = tid + h * 256;
            int rr = p >> 3, s = p & 7;
            const __nv_bfloat16* ga = g_X + (size_t)(row0 + rr) * DIM + k0 + s * 8;
            uint32_t sa = (uint32_t)__cvta_generic_to_shared(
                &sm[buf * ABUF + rr * 64 + ((s ^ (rr & 7)) << 3)]);
            asm volatile("cp.async.cg.shared.global [%0], [%1], 16;" :: "r"(sa), "l"(ga));
        }
        if (!diag) {
#pragma unroll
            for (int h = 0; h < 4; ++h) {
                int p = tid + h * 256;
                int rr = p >> 3, s = p & 7;
                const __nv_bfloat16* gb = g_X + (size_t)(col0 + rr) * DIM + k0 + s * 8;
                uint32_t sb = (uint32_t)__cvta_generic_to_shared(
                    &sm[3 * ABUF + buf * ABUF + rr * 64 + ((s ^ (rr & 7)) << 3)]);
                asm volatile("cp.async.cg.shared.global [%0], [%1], 16;" :: "r"(sb), "l"(gb));
            }
        }
        asm volatile("cp.async.commit_group;");
    };

    issue(0, 0);
    issue(1, 1);

    int bufs = 0;          // rotates 0,1,2
#pragma unroll 1
    for (int it = 0; it < 16; ++it) {
        const int buf = bufs;
        bufs = (bufs == 2) ? 0 : bufs + 1;
        if (it < 15) asm volatile("cp.async.wait_group 1;");
        else         asm volatile("cp.async.wait_group 0;");
        __syncthreads();
        if (it + 2 < 16) {
            int nb = buf + 2; if (nb >= 3) nb -= 3;
            issue(it + 2, nb);
        }
#pragma unroll
        for (int kk = 0; kk < 4; ++kk) {
            uint32_t a[2][4];
#pragma unroll
            for (int mt = 0; mt < 2; ++mt) {
                int row = wr * 32 + mt * 16 + (lane & 15);
                int ch  = kk * 2 + (lane >> 4);
                uint32_t addr = (uint32_t)__cvta_generic_to_shared(
                    &sm[buf * ABUF + row * 64 + ((ch ^ (row & 7)) << 3)]);
                asm volatile("ldmatrix.sync.aligned.m8n8.x4.shared.b16 {%0,%1,%2,%3}, [%4];"
                             : "=r"(a[mt][0]), "=r"(a[mt][1]), "=r"(a[mt][2]), "=r"(a[mt][3])
                             : "r"(addr));
            }
            uint32_t b[8][2];
#pragma unroll
            for (int nt2 = 0; nt2 < 4; ++nt2) {
                int row = wc * 64 + nt2 * 16 + (lane & 7) + ((lane & 16) >> 1);
                int ch  = kk * 2 + ((lane >> 3) & 1);
                uint32_t addr = (uint32_t)__cvta_generic_to_shared(
                    &sm[bbase + buf * ABUF + row * 64 + ((ch ^ (row & 7)) << 3)]);
                uint32_t r0, r1, r2, r3;
                asm volatile("ldmatrix.sync.aligned.m8n8.x4.shared.b16 {%0,%1,%2,%3}, [%4];"
                             : "=r"(r0), "=r"(r1), "=r"(r2), "=r"(r3) : "r"(addr));
                b[2 * nt2][0] = r0; b[2 * nt2][1] = r1;
                b[2 * nt2 + 1][0] = r2; b[2 * nt2 + 1][1] = r3;
            }
#pragma unroll
            for (int mt = 0; mt < 2; ++mt)
#pragma unroll
                for (int nt = 0; nt < 8; ++nt)
                    asm volatile("mma.sync.aligned.m16n8k16.row.col.f32.bf16.bf16.f32 "
                                 "{%0,%1,%2,%3},{%4,%5,%6,%7},{%8,%9},{%0,%1,%2,%3};"
                                 : "+f"(acc[mt][nt][0]), "+f"(acc[mt][nt][1]),
                                   "+f"(acc[mt][nt][2]), "+f"(acc[mt][nt][3])
                                 : "r"(a[mt][0]), "r"(a[mt][1]), "r"(a[mt][2]), "r"(a[mt][3]),
                                   "r"(b[nt][0]), "r"(b[nt][1]));
        }
    }

    // -------- epilogue: denominator only --------
    float rowE[4] = {0.f, 0.f, 0.f, 0.f};
    float colE[16];
#pragma unroll
    for (int q = 0; q < 16; q++) colE[q] = 0.f;

    int irow[4];
#pragma unroll
    for (int rs = 0; rs < 4; rs++)
        irow[rs] = row0 + wr * 32 + (rs >> 1) * 16 + (rs & 1) * 8 + (lane >> 2);

#pragma unroll
    for (int mt = 0; mt < 2; ++mt)
#pragma unroll
        for (int nt = 0; nt < 8; ++nt)
#pragma unroll
            for (int q = 0; q < 4; ++q) {
                int rs = mt * 2 + (q >> 1);
                float e = ex2f(fmaf(acc[mt][nt][q], C1EXP, -C1EXP));
                if (tile_type != 1) {
                    int j = col0 + wc * 64 + nt * 8 + (lane & 3) * 2 + (q & 1);
                    if (tile_type == 2) { if (j >= NCOLS) e = 0.f; }
                    else                { if (j == irow[rs]) e = 0.f; }
                }
                rowE[rs] += e;
                colE[nt * 2 + (q & 1)] += e;
            }

#pragma unroll
    for (int rs = 0; rs < 4; rs++) {
        float v = rowE[rs];
        v += __shfl_xor_sync(0xffffffffu, v, 1);
        v += __shfl_xor_sync(0xffffffffu, v, 2);
        if ((lane & 3) == 0) atomicAdd(&g_acc[0][irow[rs]], v);
    }
    if (tile_type == 1) {
#pragma unroll
        for (int idx = 0; idx < 16; ++idx) {
            float v = colE[idx];
            v += __shfl_xor_sync(0xffffffffu, v, 4);
            v += __shfl_xor_sync(0xffffffffu, v, 8);
            v += __shfl_xor_sync(0xffffffffu, v, 16);
            if (lane < 4) {
                int j = col0 + wc * 64 + (idx >> 1) * 8 + lane * 2 + (idx & 1);
                atomicAdd(&g_acc[0][j], v);
            }
        }
    }
}

// ---------------- finalize + combine (single block, fast log) + cleanup ----------------
__global__ void finalize_k(float* __restrict__ out)
{
    __shared__ float red[32];
    const int tid = threadIdx.x;
    const int lane = tid & 31, wid = tid >> 5;

    float val = 0.f;
    for (int i = tid; i < NROW; i += 1024) {
        float Dn = g_acc[0][i];
        float P0 = g_acc[1][i], P1 = g_acc[2][i], Pe = g_acc[3][i];
        float Pex = g_acc[4][i], Pe2 = g_acc[5][i], Pe2x = g_acc[6][i];
        float LD = lg2f(Dn) * LN2F;
        float inv = 1.f / Dn;
        float w0 = P0 - 2.f * Pe * inv + Pe2 * inv * inv;
        float wx = P1 - 2.f * Pex * inv + Pe2x * inv * inv;
        float S = wx - LD * w0;
        float pos = (P0 < 1e-6f) ? 1.f : P0;
        float mlpp = -S / pos;
        val += g_tmask[g_lab[i]] ? mlpp : 0.f;
        g_acc[0][i] = 0.f;                     // cleanup for next replay
    }
    __syncthreads();                           // all g_tmask reads done
    for (int i = tid; i < 1000; i += 1024) { g_cnt[i] = 0; g_tmask[i] = 0; }

#pragma unroll
    for (int o = 16; o > 0; o >>= 1) val += __shfl_xor_sync(0xffffffffu, val, o);
    if (lane == 0) red[wid] = val;
    __syncthreads();
    if (wid == 0) {
        float v = (lane < 32) ? red[lane] : 0.f;
#pragma unroll
        for (int o = 16; o > 0; o >>= 1) v += __shfl_xor_sync(0xffffffffu, v, o);
        if (lane == 0) {
            out[0] = (v + g_loss2) * (1.0f / (float)NROW);
            g_loss2 = 0.f;                     // cleanup for next replay
        }
    }
}

// ---------------- launch ----------------
extern "C" void kernel_launch(void* const* d_in, const int* in_sizes, int n_in,
                              void* d_out, int out_size)
{
    const float* features = (const float*)d_in[0];
    const float* samix    = (const float*)d_in[1];
    const float* points   = (const float*)d_in[2];
    const float* lamb     = (const float*)d_in[3];
    const int*   labels   = (const int*)d_in[4];
    const int*   tlab     = (const int*)d_in[5];
    const int*   mixed    = (const int*)d_in[6];
    const int*   prevp    = (n_in > 7) ? (const int*)d_in[7] : nullptr;
    int ntl = in_sizes[5];

    static bool attr_set = false;
    if (!attr_set) {
        cudaFuncSetAttribute(gemm_pos_k, cudaFuncAttributeMaxDynamicSharedMemorySize, SMEM_SZ);
        attr_set = true;
    }

    prep_all<<<(XROWS * DIM / 4 + 255) / 256, 256>>>(features, points, labels, tlab, ntl, prevp);
    gemm_pos_k<<<GTILES + PBLKS, 256, SMEM_SZ>>>(prevp, features, samix, points, lamb, labels, mixed);
    finalize_k<<<1, 1024>>>((float*)d_out);
    (void)out_size;
}